// round 4
// baseline (speedup 1.0000x reference)
#include <cuda_runtime.h>
#include <cstdint>
#include <cstddef>

// Problem constants
#define NV     4096
#define KIN    512
#define DOUT   64
#define NHEAD  8
#define LALPHA 0.2f

// Scratch (device globals; no allocation allowed)
__device__ __align__(128) float g_Wh[(size_t)NHEAD * NV * DOUT];  // [H][N][64], 8 MB
__device__ __align__(128) float g_f1[NHEAD * NV];                 // [H][N]
__device__ __align__(128) float g_f2[NHEAD * NV];                 // [H][N]

// ---------------------------------------------------------------------------
// Kernel 1: Wh[h, n, o] = sum_i x[n,i] * W[h,i,o]
// Tile: 128 rows x 64 cols (full head width), K-chunks of 16. 256 threads,
// each computes an 8x4 microtile. ~1.07G FMA total.
// ---------------------------------------------------------------------------
__global__ __launch_bounds__(256) void wh_kernel(const float* __restrict__ x,
                                                 const float* __restrict__ W) {
    const int h  = blockIdx.y;
    const int n0 = blockIdx.x * 128;
    const int tid = threadIdx.x;

    __shared__ float xs[16][132];  // [k][row], padded
    __shared__ float ws[16][68];   // [k][col], padded (68*4 bytes, 16B-aligned rows)

    float acc[8][4];
#pragma unroll
    for (int i = 0; i < 8; i++)
#pragma unroll
        for (int j = 0; j < 4; j++) acc[i][j] = 0.f;

    const int ty = tid >> 4;   // 0..15
    const int tx = tid & 15;   // 0..15
    const float* Wp = W + (size_t)h * KIN * DOUT;

    for (int k0 = 0; k0 < KIN; k0 += 16) {
        // load x tile [128 rows x 16 k] (512 float4s, 2 per thread)
#pragma unroll
        for (int l = 0; l < 2; l++) {
            int fidx = tid + l * 256;
            int r = fidx >> 2, kq = fidx & 3;
            float4 v = *(const float4*)(x + (size_t)(n0 + r) * KIN + k0 + kq * 4);
            xs[kq * 4 + 0][r] = v.x;
            xs[kq * 4 + 1][r] = v.y;
            xs[kq * 4 + 2][r] = v.z;
            xs[kq * 4 + 3][r] = v.w;
        }
        // load W tile [16 k x 64 o] (one float4 per thread)
        {
            float4 v = *(const float4*)(Wp + (size_t)(k0 + ty) * DOUT + tx * 4);
            *(float4*)&ws[ty][tx * 4] = v;
        }
        __syncthreads();

#pragma unroll
        for (int k = 0; k < 16; k++) {
            float4 a0 = *(const float4*)&xs[k][ty * 8];
            float4 a1v = *(const float4*)&xs[k][ty * 8 + 4];
            float4 bv = *(const float4*)&ws[k][tx * 4];
            float av[8] = {a0.x, a0.y, a0.z, a0.w, a1v.x, a1v.y, a1v.z, a1v.w};
            float bb[4] = {bv.x, bv.y, bv.z, bv.w};
#pragma unroll
            for (int i = 0; i < 8; i++)
#pragma unroll
                for (int j = 0; j < 4; j++) acc[i][j] += av[i] * bb[j];
        }
        __syncthreads();
    }

    float* op = g_Wh + ((size_t)h * NV + n0) * DOUT;
#pragma unroll
    for (int i = 0; i < 8; i++) {
        int r = ty * 8 + i;
        float4 v = make_float4(acc[i][0], acc[i][1], acc[i][2], acc[i][3]);
        *(float4*)(op + (size_t)r * DOUT + tx * 4) = v;
    }
}

// ---------------------------------------------------------------------------
// Kernel 2: f1[h,n] = Wh[h,n,:] . a1[h,:],  f2 likewise. One warp per (h,n).
// ---------------------------------------------------------------------------
__global__ __launch_bounds__(256) void fvec_kernel(const float* __restrict__ a1,
                                                   const float* __restrict__ a2) {
    int gw = (blockIdx.x * blockDim.x + threadIdx.x) >> 5;  // global warp
    int lane = threadIdx.x & 31;
    if (gw >= NHEAD * NV) return;
    int h = gw & 7;
    int n = gw >> 3;

    const float* wr = g_Wh + ((size_t)h * NV + n) * DOUT;
    float w0 = wr[lane], w1 = wr[lane + 32];
    float s1 = w0 * a1[h * DOUT + lane] + w1 * a1[h * DOUT + lane + 32];
    float s2 = w0 * a2[h * DOUT + lane] + w1 * a2[h * DOUT + lane + 32];
#pragma unroll
    for (int off = 16; off; off >>= 1) {
        s1 += __shfl_xor_sync(0xffffffffu, s1, off);
        s2 += __shfl_xor_sync(0xffffffffu, s2, off);
    }
    if (lane == 0) {
        g_f1[h * NV + n] = s1;
        g_f2[h * NV + n] = s2;
    }
}

// ---------------------------------------------------------------------------
// Kernel 3: fused masked softmax + aggregation.
// CTA = (head, 64-row tile). Pass 1: read adj row once, build bitmask in smem
// + per-row max of f2 over neighbors (exact softmax max via lrelu monotonicity).
// Pass 2: 64-wide m-chunks: P tile -> smem, mini-GEMM P @ Wh (4x4 microtiles).
// ---------------------------------------------------------------------------
// Dynamic smem layout (bytes):
//   f2s    : 4096 f         @ 0        (16384)
//   maskT  : 128*64 u32     @ 16384    (32768)   word wi=(m>>7)*4+(m&3), bit=(m&127)>>2
//   ps     : 64*72 f        @ 49152    (18432)   [mm][r], padded
//   whs    : 64*72 f        @ 67584    (18432)   [mm][o], padded
//   f1s    : 64 f           @ 86016
//   Ms     : 64 f
//   maxf2  : 64 f
//   denomS : 64 f
//   denP   : 256 f
#define SMEM3_BYTES (16384 + 32768 + 18432 + 18432 + (64 + 64 + 64 + 64 + 256) * 4)

__global__ __launch_bounds__(256, 2) void attn_kernel(const int* __restrict__ adj,
                                                      float* __restrict__ out) {
    extern __shared__ unsigned char smem_raw[];
    float*    f2s    = (float*)smem_raw;
    unsigned* maskT  = (unsigned*)(smem_raw + 16384);
    float*    ps     = (float*)(smem_raw + 49152);
    float*    whs    = (float*)(smem_raw + 67584);
    float*    f1s    = (float*)(smem_raw + 86016);
    float*    Ms     = f1s + 64;
    float*    maxf2  = Ms + 64;
    float*    denomS = maxf2 + 64;
    float*    denP   = denomS + 64;

    const int h   = blockIdx.x;
    const int n0  = blockIdx.y * 64;
    const int tid = threadIdx.x;

    // stage f2[h,:] and f1[h, n0..n0+63]
    {
        const float4* src = (const float4*)(g_f2 + (size_t)h * NV);
        float4* dst = (float4*)f2s;
        for (int i = tid; i < NV / 4; i += 256) dst[i] = src[i];
    }
    if (tid < 64) f1s[tid] = g_f1[(size_t)h * NV + n0 + tid];
    __syncthreads();

    // ---- pass 1: adjacency scan (bitmask + per-row max of f2 over neighbors)
    const int warp = tid >> 5, lane = tid & 31;
    for (int j = 0; j < 8; j++) {
        int r = warp * 8 + j;
        const uint4* arow = (const uint4*)(adj + (size_t)(n0 + r) * NV);
        float mx = -3.4e38f;
#pragma unroll 2
        for (int g = 0; g < 32; g++) {
            uint4 v = arow[g * 32 + lane];         // m = g*128 + lane*4 + {0..3}
            float4 fv = *(const float4*)(f2s + g * 128 + lane * 4);
            unsigned b0 = __ballot_sync(0xffffffffu, (int)v.x > 0);
            unsigned b1 = __ballot_sync(0xffffffffu, (int)v.y > 0);
            unsigned b2 = __ballot_sync(0xffffffffu, (int)v.z > 0);
            unsigned b3 = __ballot_sync(0xffffffffu, (int)v.w > 0);
            if ((int)v.x > 0) mx = fmaxf(mx, fv.x);
            if ((int)v.y > 0) mx = fmaxf(mx, fv.y);
            if ((int)v.z > 0) mx = fmaxf(mx, fv.z);
            if ((int)v.w > 0) mx = fmaxf(mx, fv.w);
            if (lane == 0) {
                maskT[(g * 4 + 0) * 64 + r] = b0;
                maskT[(g * 4 + 1) * 64 + r] = b1;
                maskT[(g * 4 + 2) * 64 + r] = b2;
                maskT[(g * 4 + 3) * 64 + r] = b3;
            }
        }
#pragma unroll
        for (int off = 16; off; off >>= 1)
            mx = fmaxf(mx, __shfl_xor_sync(0xffffffffu, mx, off));
        if (lane == 0) maxf2[r] = mx;
    }
    __syncthreads();
    if (tid < 64) {
        float s = f1s[tid] + maxf2[tid];      // lrelu monotone -> exact row max
        Ms[tid] = s > 0.f ? s : LALPHA * s;
    }
    __syncthreads();

    // ---- pass 2: chunked softmax numerator + aggregation
    const int rA   = tid & 63;   // phase-A row (fixed per thread across chunks)
    const int mmHi = tid >> 6;   // 0..3
    const float f1r = f1s[rA];
    const float Mr  = Ms[rA];
    float den = 0.f;

    const int ty = tid >> 4, tx = tid & 15;  // phase-B microtile coords
    float acc[4][4];
#pragma unroll
    for (int i = 0; i < 4; i++)
#pragma unroll
        for (int jj = 0; jj < 4; jj++) acc[i][jj] = 0.f;

    const float* WhH = g_Wh + (size_t)h * NV * DOUT;

    for (int c = 0; c < 64; c++) {
        const int m0 = c * 64;

        // issue Wh-tile loads first (MLP=4), overlap with phase A
        float4 wreg[4];
#pragma unroll
        for (int l = 0; l < 4; l++) {
            int fidx = tid + l * 256;              // 0..1023
            int mm = fidx >> 4, oq = fidx & 15;
            wreg[l] = *(const float4*)(WhH + (size_t)(m0 + mm) * DOUT + oq * 4);
        }

        // phase A: P tile [mm][r]
#pragma unroll
        for (int k = 0; k < 16; k++) {
            int mm = mmHi * 16 + k;
            int m = m0 + mm;
            unsigned w = maskT[((m >> 7) * 4 + (m & 3)) * 64 + rA];
            unsigned bit = (w >> ((m & 127) >> 2)) & 1u;
            float s = f1r + f2s[m];
            s = s > 0.f ? s : LALPHA * s;
            float p = bit ? __expf(s - Mr) : 0.f;
            den += p;
            ps[mm * 72 + rA] = p;
        }
        // stash Wh tile to smem
#pragma unroll
        for (int l = 0; l < 4; l++) {
            int fidx = tid + l * 256;
            int mm = fidx >> 4, oq = fidx & 15;
            *(float4*)(whs + mm * 72 + oq * 4) = wreg[l];
        }
        __syncthreads();

        // phase B: acc[r][o] += P[r][m] * Wh[m][o]
#pragma unroll 4
        for (int m = 0; m < 64; m++) {
            float4 av = *(const float4*)(ps + m * 72 + ty * 4);
            float4 bv = *(const float4*)(whs + m * 72 + tx * 4);
            float aa[4] = {av.x, av.y, av.z, av.w};
            float bb[4] = {bv.x, bv.y, bv.z, bv.w};
#pragma unroll
            for (int i = 0; i < 4; i++)
#pragma unroll
                for (int jj = 0; jj < 4; jj++) acc[i][jj] += aa[i] * bb[jj];
        }
        __syncthreads();
    }

    // denominators
    denP[mmHi * 64 + rA] = den;
    __syncthreads();
    if (tid < 64) {
        float d = denP[tid] + denP[64 + tid] + denP[128 + tid] + denP[192 + tid];
        denomS[tid] = d > 0.f ? 1.f / d : 0.f;
    }
    __syncthreads();

    // writeback: out[n, h*64+o]
#pragma unroll
    for (int i = 0; i < 4; i++) {
        int r = ty * 4 + i;
        float inv = denomS[r];
        float4 v = make_float4(acc[i][0] * inv, acc[i][1] * inv,
                               acc[i][2] * inv, acc[i][3] * inv);
        *(float4*)(out + (size_t)(n0 + r) * (NHEAD * DOUT) + h * DOUT + tx * 4) = v;
    }
}

// ---------------------------------------------------------------------------
extern "C" void kernel_launch(void* const* d_in, const int* in_sizes, int n_in,
                              void* d_out, int out_size) {
    (void)in_sizes; (void)n_in; (void)out_size;
    const float* x   = (const float*)d_in[0];
    const int*   adj = (const int*)d_in[1];
    const float* W   = (const float*)d_in[2];
    const float* a1  = (const float*)d_in[3];
    const float* a2  = (const float*)d_in[4];
    float* out = (float*)d_out;

    cudaFuncSetAttribute(attn_kernel, cudaFuncAttributeMaxDynamicSharedMemorySize,
                         SMEM3_BYTES);

    wh_kernel<<<dim3(32, 8), 256>>>(x, W);
    fvec_kernel<<<4096, 256>>>(a1, a2);
    attn_kernel<<<dim3(8, 64), 256, SMEM3_BYTES>>>(adj, out);
}

// round 6
// speedup vs baseline: 1.0047x; 1.0047x over previous
#include <cuda_runtime.h>
#include <cstdint>
#include <cstddef>

// Problem constants
#define NV     4096
#define KIN    512
#define DOUT   64
#define NHEAD  8
#define LALPHA 0.2f

// Scratch (device globals; no allocation allowed)
__device__ __align__(128) float g_Wh[(size_t)NHEAD * NV * DOUT];  // [H][N][64], 8 MB
__device__ __align__(128) float g_f1[NHEAD * NV];                 // [H][N]
__device__ __align__(128) float g_f2[NHEAD * NV];                 // [H][N]

// ---------------------------------------------------------------------------
// Kernel 1: Wh[h, n, o] = sum_i x[n,i] * W[h,i,o]
// Tile: 128 rows x 64 cols (full head width), K-chunks of 16. 256 threads,
// each computes an 8x4 microtile. ~1.07G FMA total.
// ---------------------------------------------------------------------------
__global__ __launch_bounds__(256) void wh_kernel(const float* __restrict__ x,
                                                 const float* __restrict__ W) {
    const int h  = blockIdx.y;
    const int n0 = blockIdx.x * 128;
    const int tid = threadIdx.x;

    __shared__ float xs[16][132];  // [k][row], padded
    __shared__ float ws[16][68];   // [k][col], padded (68*4 bytes, 16B-aligned rows)

    float acc[8][4];
#pragma unroll
    for (int i = 0; i < 8; i++)
#pragma unroll
        for (int j = 0; j < 4; j++) acc[i][j] = 0.f;

    const int ty = tid >> 4;   // 0..15
    const int tx = tid & 15;   // 0..15
    const float* Wp = W + (size_t)h * KIN * DOUT;

    for (int k0 = 0; k0 < KIN; k0 += 16) {
        // load x tile [128 rows x 16 k] (512 float4s, 2 per thread)
#pragma unroll
        for (int l = 0; l < 2; l++) {
            int fidx = tid + l * 256;
            int r = fidx >> 2, kq = fidx & 3;
            float4 v = *(const float4*)(x + (size_t)(n0 + r) * KIN + k0 + kq * 4);
            xs[kq * 4 + 0][r] = v.x;
            xs[kq * 4 + 1][r] = v.y;
            xs[kq * 4 + 2][r] = v.z;
            xs[kq * 4 + 3][r] = v.w;
        }
        // load W tile [16 k x 64 o] (one float4 per thread)
        {
            float4 v = *(const float4*)(Wp + (size_t)(k0 + ty) * DOUT + tx * 4);
            *(float4*)&ws[ty][tx * 4] = v;
        }
        __syncthreads();

#pragma unroll
        for (int k = 0; k < 16; k++) {
            float4 a0 = *(const float4*)&xs[k][ty * 8];
            float4 a1v = *(const float4*)&xs[k][ty * 8 + 4];
            float4 bv = *(const float4*)&ws[k][tx * 4];
            float av[8] = {a0.x, a0.y, a0.z, a0.w, a1v.x, a1v.y, a1v.z, a1v.w};
            float bb[4] = {bv.x, bv.y, bv.z, bv.w};
#pragma unroll
            for (int i = 0; i < 8; i++)
#pragma unroll
                for (int j = 0; j < 4; j++) acc[i][j] += av[i] * bb[j];
        }
        __syncthreads();
    }

    float* op = g_Wh + ((size_t)h * NV + n0) * DOUT;
#pragma unroll
    for (int i = 0; i < 8; i++) {
        int r = ty * 8 + i;
        float4 v = make_float4(acc[i][0], acc[i][1], acc[i][2], acc[i][3]);
        *(float4*)(op + (size_t)r * DOUT + tx * 4) = v;
    }
}

// ---------------------------------------------------------------------------
// Kernel 2: f1[h,n] = Wh[h,n,:] . a1[h,:],  f2 likewise. One warp per (h,n).
// ---------------------------------------------------------------------------
__global__ __launch_bounds__(256) void fvec_kernel(const float* __restrict__ a1,
                                                   const float* __restrict__ a2) {
    int gw = (blockIdx.x * blockDim.x + threadIdx.x) >> 5;  // global warp
    int lane = threadIdx.x & 31;
    if (gw >= NHEAD * NV) return;
    int h = gw & 7;
    int n = gw >> 3;

    const float* wr = g_Wh + ((size_t)h * NV + n) * DOUT;
    float w0 = wr[lane], w1 = wr[lane + 32];
    float s1 = w0 * a1[h * DOUT + lane] + w1 * a1[h * DOUT + lane + 32];
    float s2 = w0 * a2[h * DOUT + lane] + w1 * a2[h * DOUT + lane + 32];
#pragma unroll
    for (int off = 16; off; off >>= 1) {
        s1 += __shfl_xor_sync(0xffffffffu, s1, off);
        s2 += __shfl_xor_sync(0xffffffffu, s2, off);
    }
    if (lane == 0) {
        g_f1[h * NV + n] = s1;
        g_f2[h * NV + n] = s2;
    }
}

// ---------------------------------------------------------------------------
// Kernel 3: fused masked softmax + aggregation.
// CTA = (head, 64-row tile). Pass 1: read adj row once, build bitmask in smem
// + per-row max of f2 over neighbors (exact softmax max via lrelu monotonicity).
// Pass 2: 64-wide m-chunks: P tile -> smem, mini-GEMM P @ Wh (4x4 microtiles).
// ---------------------------------------------------------------------------
// Dynamic smem layout (bytes):
//   f2s    : 4096 f         @ 0        (16384)
//   maskT  : 128*64 u32     @ 16384    (32768)   word wi=(m>>7)*4+(m&3), bit=(m&127)>>2
//   ps     : 64*72 f        @ 49152    (18432)   [mm][r], padded
//   whs    : 64*72 f        @ 67584    (18432)   [mm][o], padded
//   f1s    : 64 f           @ 86016
//   Ms     : 64 f
//   maxf2  : 64 f
//   denomS : 64 f
//   denP   : 256 f
#define SMEM3_BYTES (16384 + 32768 + 18432 + 18432 + (64 + 64 + 64 + 64 + 256) * 4)

__global__ __launch_bounds__(256, 2) void attn_kernel(const int* __restrict__ adj,
                                                      float* __restrict__ out) {
    extern __shared__ unsigned char smem_raw[];
    float*    f2s    = (float*)smem_raw;
    unsigned* maskT  = (unsigned*)(smem_raw + 16384);
    float*    ps     = (float*)(smem_raw + 49152);
    float*    whs    = (float*)(smem_raw + 67584);
    float*    f1s    = (float*)(smem_raw + 86016);
    float*    Ms     = f1s + 64;
    float*    maxf2  = Ms + 64;
    float*    denomS = maxf2 + 64;
    float*    denP   = denomS + 64;

    const int h   = blockIdx.x;
    const int n0  = blockIdx.y * 64;
    const int tid = threadIdx.x;

    // stage f2[h,:] and f1[h, n0..n0+63]
    {
        const float4* src = (const float4*)(g_f2 + (size_t)h * NV);
        float4* dst = (float4*)f2s;
        for (int i = tid; i < NV / 4; i += 256) dst[i] = src[i];
    }
    if (tid < 64) f1s[tid] = g_f1[(size_t)h * NV + n0 + tid];
    __syncthreads();

    // ---- pass 1: adjacency scan (bitmask + per-row max of f2 over neighbors)
    const int warp = tid >> 5, lane = tid & 31;
    for (int j = 0; j < 8; j++) {
        int r = warp * 8 + j;
        const uint4* arow = (const uint4*)(adj + (size_t)(n0 + r) * NV);
        float mx = -3.4e38f;
#pragma unroll 2
        for (int g = 0; g < 32; g++) {
            uint4 v = arow[g * 32 + lane];         // m = g*128 + lane*4 + {0..3}
            float4 fv = *(const float4*)(f2s + g * 128 + lane * 4);
            unsigned b0 = __ballot_sync(0xffffffffu, (int)v.x > 0);
            unsigned b1 = __ballot_sync(0xffffffffu, (int)v.y > 0);
            unsigned b2 = __ballot_sync(0xffffffffu, (int)v.z > 0);
            unsigned b3 = __ballot_sync(0xffffffffu, (int)v.w > 0);
            if ((int)v.x > 0) mx = fmaxf(mx, fv.x);
            if ((int)v.y > 0) mx = fmaxf(mx, fv.y);
            if ((int)v.z > 0) mx = fmaxf(mx, fv.z);
            if ((int)v.w > 0) mx = fmaxf(mx, fv.w);
            if (lane == 0) {
                maskT[(g * 4 + 0) * 64 + r] = b0;
                maskT[(g * 4 + 1) * 64 + r] = b1;
                maskT[(g * 4 + 2) * 64 + r] = b2;
                maskT[(g * 4 + 3) * 64 + r] = b3;
            }
        }
#pragma unroll
        for (int off = 16; off; off >>= 1)
            mx = fmaxf(mx, __shfl_xor_sync(0xffffffffu, mx, off));
        if (lane == 0) maxf2[r] = mx;
    }
    __syncthreads();
    if (tid < 64) {
        float s = f1s[tid] + maxf2[tid];      // lrelu monotone -> exact row max
        Ms[tid] = s > 0.f ? s : LALPHA * s;
    }
    __syncthreads();

    // ---- pass 2: chunked softmax numerator + aggregation
    const int rA   = tid & 63;   // phase-A row (fixed per thread across chunks)
    const int mmHi = tid >> 6;   // 0..3
    const float f1r = f1s[rA];
    const float Mr  = Ms[rA];
    float den = 0.f;

    const int ty = tid >> 4, tx = tid & 15;  // phase-B microtile coords
    float acc[4][4];
#pragma unroll
    for (int i = 0; i < 4; i++)
#pragma unroll
        for (int jj = 0; jj < 4; jj++) acc[i][jj] = 0.f;

    const float* WhH = g_Wh + (size_t)h * NV * DOUT;

    for (int c = 0; c < 64; c++) {
        const int m0 = c * 64;

        // issue Wh-tile loads first (MLP=4), overlap with phase A
        float4 wreg[4];
#pragma unroll
        for (int l = 0; l < 4; l++) {
            int fidx = tid + l * 256;              // 0..1023
            int mm = fidx >> 4, oq = fidx & 15;
            wreg[l] = *(const float4*)(WhH + (size_t)(m0 + mm) * DOUT + oq * 4);
        }

        // phase A: P tile [mm][r]
#pragma unroll
        for (int k = 0; k < 16; k++) {
            int mm = mmHi * 16 + k;
            int m = m0 + mm;
            unsigned w = maskT[((m >> 7) * 4 + (m & 3)) * 64 + rA];
            unsigned bit = (w >> ((m & 127) >> 2)) & 1u;
            float s = f1r + f2s[m];
            s = s > 0.f ? s : LALPHA * s;
            float p = bit ? __expf(s - Mr) : 0.f;
            den += p;
            ps[mm * 72 + rA] = p;
        }
        // stash Wh tile to smem
#pragma unroll
        for (int l = 0; l < 4; l++) {
            int fidx = tid + l * 256;
            int mm = fidx >> 4, oq = fidx & 15;
            *(float4*)(whs + mm * 72 + oq * 4) = wreg[l];
        }
        __syncthreads();

        // phase B: acc[r][o] += P[r][m] * Wh[m][o]
#pragma unroll 4
        for (int m = 0; m < 64; m++) {
            float4 av = *(const float4*)(ps + m * 72 + ty * 4);
            float4 bv = *(const float4*)(whs + m * 72 + tx * 4);
            float aa[4] = {av.x, av.y, av.z, av.w};
            float bb[4] = {bv.x, bv.y, bv.z, bv.w};
#pragma unroll
            for (int i = 0; i < 4; i++)
#pragma unroll
                for (int jj = 0; jj < 4; jj++) acc[i][jj] += aa[i] * bb[jj];
        }
        __syncthreads();
    }

    // denominators
    denP[mmHi * 64 + rA] = den;
    __syncthreads();
    if (tid < 64) {
        float d = denP[tid] + denP[64 + tid] + denP[128 + tid] + denP[192 + tid];
        denomS[tid] = d > 0.f ? 1.f / d : 0.f;
    }
    __syncthreads();

    // writeback: out[n, h*64+o]
#pragma unroll
    for (int i = 0; i < 4; i++) {
        int r = ty * 4 + i;
        float inv = denomS[r];
        float4 v = make_float4(acc[i][0] * inv, acc[i][1] * inv,
                               acc[i][2] * inv, acc[i][3] * inv);
        *(float4*)(out + (size_t)(n0 + r) * (NHEAD * DOUT) + h * DOUT + tx * 4) = v;
    }
}

// ---------------------------------------------------------------------------
extern "C" void kernel_launch(void* const* d_in, const int* in_sizes, int n_in,
                              void* d_out, int out_size) {
    (void)in_sizes; (void)n_in; (void)out_size;
    const float* x   = (const float*)d_in[0];
    const int*   adj = (const int*)d_in[1];
    const float* W   = (const float*)d_in[2];
    const float* a1  = (const float*)d_in[3];
    const float* a2  = (const float*)d_in[4];
    float* out = (float*)d_out;

    cudaFuncSetAttribute(attn_kernel, cudaFuncAttributeMaxDynamicSharedMemorySize,
                         SMEM3_BYTES);

    wh_kernel<<<dim3(32, 8), 256>>>(x, W);
    fvec_kernel<<<4096, 256>>>(a1, a2);
    attn_kernel<<<dim3(8, 64), 256, SMEM3_BYTES>>>(adj, out);
}

// round 9
// speedup vs baseline: 3.2600x; 3.2449x over previous
#include <cuda_runtime.h>
#include <cuda_fp16.h>
#include <cstdint>
#include <cstddef>

// Problem constants
#define NV     4096
#define KIN    512
#define DOUT   64
#define NHEAD  8
#define LALPHA 0.2f

// ---------------------------------------------------------------------------
// Device scratch (no allocations allowed)
// ---------------------------------------------------------------------------
__device__ __align__(128) float    g_Wh[(size_t)NHEAD * NV * DOUT];    // fp32 [H][N][64]
__device__ __align__(128) __half   g_Wh16[(size_t)NHEAD * NV * DOUT];  // fp16 [H][N][64]
__device__ __align__(128) float    g_f1[NHEAD * NV];
__device__ __align__(128) float    g_f2[NHEAD * NV];
__device__ __align__(128) float    g_F2max[NHEAD];
__device__ __align__(128) unsigned g_mask[(size_t)NV * (NV / 32)];     // [N][128] words

// ---------------------------------------------------------------------------
// sm_80-era tensor-core PTX (valid on base sm_103 target)
// ---------------------------------------------------------------------------
__device__ __forceinline__ uint32_t smem_u32(const void* p) {
    uint32_t a;
    asm("{ .reg .u64 t; cvta.to.shared.u64 t, %1; cvt.u32.u64 %0, t; }"
        : "=r"(a) : "l"(p));
    return a;
}

#define LDSM_X4(r, a) \
    asm volatile("ldmatrix.sync.aligned.m8n8.x4.shared.b16 {%0,%1,%2,%3}, [%4];" \
        : "=r"((r)[0]), "=r"((r)[1]), "=r"((r)[2]), "=r"((r)[3]) : "r"(a))

#define LDSM_X4T(r, a) \
    asm volatile("ldmatrix.sync.aligned.m8n8.x4.trans.shared.b16 {%0,%1,%2,%3}, [%4];" \
        : "=r"((r)[0]), "=r"((r)[1]), "=r"((r)[2]), "=r"((r)[3]) : "r"(a))

#define MMA16816(d, a, b) \
    asm volatile("mma.sync.aligned.m16n8k16.row.col.f32.f16.f16.f32 " \
        "{%0,%1,%2,%3}, {%4,%5,%6,%7}, {%8,%9}, {%0,%1,%2,%3};" \
        : "+f"((d)[0]), "+f"((d)[1]), "+f"((d)[2]), "+f"((d)[3]) \
        : "r"((a)[0]), "r"((a)[1]), "r"((a)[2]), "r"((a)[3]), \
          "r"((b)[0]), "r"((b)[1]))

// ---------------------------------------------------------------------------
// Kernel: adj -> bitmask (word w covers m = w*32..+31, bit = lane)
// ---------------------------------------------------------------------------
__global__ __launch_bounds__(256) void mask_kernel(const int* __restrict__ adj) {
    int gw   = (blockIdx.x * 256 + threadIdx.x) >> 5;
    int lane = threadIdx.x & 31;
    int nw   = (gridDim.x * 256) >> 5;
    for (int w = gw; w < NV * (NV / 32); w += nw) {
        int v = adj[(size_t)w * 32 + lane];
        unsigned b = __ballot_sync(0xffffffffu, v > 0);
        if (lane == 0) g_mask[w] = b;
    }
}

// ---------------------------------------------------------------------------
// Kernel 1: Wh[h,n,o] = sum_i x[n,i] * W[h,i,o]  (fp32; also writes fp16 copy)
// ---------------------------------------------------------------------------
__global__ __launch_bounds__(256) void wh_kernel(const float* __restrict__ x,
                                                 const float* __restrict__ W) {
    const int h  = blockIdx.y;
    const int n0 = blockIdx.x * 128;
    const int tid = threadIdx.x;

    __shared__ float xs[16][132];
    __shared__ float ws[16][68];

    float acc[8][4];
#pragma unroll
    for (int i = 0; i < 8; i++)
#pragma unroll
        for (int j = 0; j < 4; j++) acc[i][j] = 0.f;

    const int ty = tid >> 4, tx = tid & 15;
    const float* Wp = W + (size_t)h * KIN * DOUT;

    for (int k0 = 0; k0 < KIN; k0 += 16) {
#pragma unroll
        for (int l = 0; l < 2; l++) {
            int fidx = tid + l * 256;
            int r = fidx >> 2, kq = fidx & 3;
            float4 v = *(const float4*)(x + (size_t)(n0 + r) * KIN + k0 + kq * 4);
            xs[kq * 4 + 0][r] = v.x;
            xs[kq * 4 + 1][r] = v.y;
            xs[kq * 4 + 2][r] = v.z;
            xs[kq * 4 + 3][r] = v.w;
        }
        {
            float4 v = *(const float4*)(Wp + (size_t)(k0 + ty) * DOUT + tx * 4);
            *(float4*)&ws[ty][tx * 4] = v;
        }
        __syncthreads();
#pragma unroll
        for (int k = 0; k < 16; k++) {
            float4 a0 = *(const float4*)&xs[k][ty * 8];
            float4 a1v = *(const float4*)&xs[k][ty * 8 + 4];
            float4 bv = *(const float4*)&ws[k][tx * 4];
            float av[8] = {a0.x, a0.y, a0.z, a0.w, a1v.x, a1v.y, a1v.z, a1v.w};
            float bb[4] = {bv.x, bv.y, bv.z, bv.w};
#pragma unroll
            for (int i = 0; i < 8; i++)
#pragma unroll
                for (int j = 0; j < 4; j++) acc[i][j] += av[i] * bb[j];
        }
        __syncthreads();
    }

    float*  op  = g_Wh   + ((size_t)h * NV + n0) * DOUT;
    __half* op16 = g_Wh16 + ((size_t)h * NV + n0) * DOUT;
#pragma unroll
    for (int i = 0; i < 8; i++) {
        int r = ty * 8 + i;
        float4 v = make_float4(acc[i][0], acc[i][1], acc[i][2], acc[i][3]);
        *(float4*)(op + (size_t)r * DOUT + tx * 4) = v;
        __half2 h01 = __floats2half2_rn(v.x, v.y);
        __half2 h23 = __floats2half2_rn(v.z, v.w);
        *(__half2*)(op16 + (size_t)r * DOUT + tx * 4)     = h01;
        *(__half2*)(op16 + (size_t)r * DOUT + tx * 4 + 2) = h23;
    }
}

// ---------------------------------------------------------------------------
// Kernel 2: f1/f2 per (h,n)
// ---------------------------------------------------------------------------
__global__ __launch_bounds__(256) void fvec_kernel(const float* __restrict__ a1,
                                                   const float* __restrict__ a2) {
    int gw = (blockIdx.x * 256 + threadIdx.x) >> 5;
    int lane = threadIdx.x & 31;
    if (gw >= NHEAD * NV) return;
    int h = gw & 7, n = gw >> 3;
    const float* wr = g_Wh + ((size_t)h * NV + n) * DOUT;
    float w0 = wr[lane], w1 = wr[lane + 32];
    float s1 = w0 * a1[h * DOUT + lane] + w1 * a1[h * DOUT + lane + 32];
    float s2 = w0 * a2[h * DOUT + lane] + w1 * a2[h * DOUT + lane + 32];
#pragma unroll
    for (int off = 16; off; off >>= 1) {
        s1 += __shfl_xor_sync(0xffffffffu, s1, off);
        s2 += __shfl_xor_sync(0xffffffffu, s2, off);
    }
    if (lane == 0) {
        g_f1[h * NV + n] = s1;
        g_f2[h * NV + n] = s2;
    }
}

__global__ void f2max_kernel() {
    __shared__ float red[256];
    int h = blockIdx.x;
    float m = -3.4e38f;
    for (int i = threadIdx.x; i < NV; i += 256) m = fmaxf(m, g_f2[h * NV + i]);
    red[threadIdx.x] = m;
    __syncthreads();
    for (int s = 128; s; s >>= 1) {
        if (threadIdx.x < s) red[threadIdx.x] = fmaxf(red[threadIdx.x], red[threadIdx.x + s]);
        __syncthreads();
    }
    if (threadIdx.x == 0) g_F2max[h] = red[0];
}

// ---------------------------------------------------------------------------
// Kernel 3: fused softmax + aggregation via mma.sync (HMMA).
// CTA = (head, 128-row tile); 64 chunks of 64 m.
//   p = exp(lrelu(f1+f2) - Mr) = max(c1*E1[m], c2*E05[m])   (exact; all <= 1)
//   E1 = exp(f2 - F2max), E05 = exp(0.2(f2 - F2max))  staged per CTA
//   chunk: build P[128x64] fp16 + Wh[64x64] fp16 tiles -> 8 warps mma.sync
// ---------------------------------------------------------------------------
#define PP 72   /* P tile pitch in halves (144 B rows: ldmatrix conflict-free) */
#define WP 72   /* Wh tile pitch in halves */

#define SM_E1   0
#define SM_E05  16384
#define SM_MASK 32768
#define SM_P    98304     /* 128*72*2 = 18432 */
#define SM_W    116736    /* 64*72*2 = 9216  */
#define SM_DEN  125952    /* 128 floats */
#define SMEM_ATT 126496

__global__ __launch_bounds__(256) void attn_mma(float* __restrict__ out) {
    extern __shared__ unsigned char sm[];
    float*    E1s   = (float*)(sm + SM_E1);
    float*    E05s  = (float*)(sm + SM_E05);
    unsigned* maskS = (unsigned*)(sm + SM_MASK);
    float*    denS  = (float*)(sm + SM_DEN);

    const int h = blockIdx.x, n0 = blockIdx.y * 128;
    const int tid = threadIdx.x, wid = tid >> 5, lane = tid & 31;

    const uint32_t Pb = smem_u32(sm + SM_P);
    const uint32_t Wb = smem_u32(sm + SM_W);

    // stage E1/E05 (from f2 + global head max) and mask rows
    const float F2m = g_F2max[h];
    for (int i = tid; i < NV; i += 256) {
        float d = g_f2[(size_t)h * NV + i] - F2m;
        E1s[i]  = __expf(d);
        E05s[i] = __expf(LALPHA * d);
    }
#pragma unroll
    for (int l = 0; l < 16; l++) {
        int i = tid + l * 256;
        ((uint4*)maskS)[i] = ((const uint4*)(g_mask + (size_t)n0 * 128))[i];
    }
    __syncthreads();

    // per-row constants (warp wid owns rows wid*16..+15 for P-gen)
    float c1[16], c2[16], den[16];
#pragma unroll
    for (int k = 0; k < 16; k++) {
        float f1v = g_f1[(size_t)h * NV + n0 + wid * 16 + k];
        float t = f1v + F2m;
        float Mr = fmaxf(t, LALPHA * t);
        c1[k] = __expf(t - Mr);            // == 1 when t > 0
        c2[k] = __expf(LALPHA * t - Mr);
        den[k] = 0.f;
    }

    // mma warp layout: 4 warps along M (32 rows) x 2 along N (32 cols)
    const int mblk = (wid & 3) * 32, nblk = (wid >> 2) * 32;
    float acc[2][4][4];
#pragma unroll
    for (int i = 0; i < 2; i++)
#pragma unroll
        for (int j = 0; j < 4; j++)
#pragma unroll
            for (int q = 0; q < 4; q++) acc[i][j][q] = 0.f;

    const __half* WhH = g_Wh16 + (size_t)h * NV * DOUT;

    for (int c = 0; c < 64; c++) {
        // Wh chunk loads (rows c*64..+63, 64 halves each) into registers first
        uint4 bv[2];
#pragma unroll
        for (int l = 0; l < 2; l++) {
            int idx = tid + l * 256;            // 0..511
            int m = idx >> 3, q = idx & 7;
            bv[l] = *(const uint4*)(WhH + (size_t)(c * 64 + m) * DOUT + q * 8);
        }

        // P tile: warp wid -> rows wid*16..+15; lane -> m-pair (2*lane, 2*lane+1)
        float2 e1p  = *(const float2*)(E1s  + c * 64 + 2 * lane);
        float2 e05p = *(const float2*)(E05s + c * 64 + 2 * lane);
#pragma unroll
        for (int k = 0; k < 16; k++) {
            int r = wid * 16 + k;
            unsigned w = maskS[r * 128 + c * 2 + (lane >> 4)];
            float p0 = fmaxf(c1[k] * e1p.x,  c2[k] * e05p.x);
            float p1 = fmaxf(c1[k] * e1p.y,  c2[k] * e05p.y);
            p0 = ((w >> ((2 * lane) & 31)) & 1u) ? p0 : 0.f;
            p1 = ((w >> ((2 * lane + 1) & 31)) & 1u) ? p1 : 0.f;
            den[k] += p0 + p1;
            *(__half2*)(sm + SM_P + (r * PP + 2 * lane) * 2) =
                __floats2half2_rn(p0, p1);
        }

        // Wh tile store
#pragma unroll
        for (int l = 0; l < 2; l++) {
            int idx = tid + l * 256;
            int m = idx >> 3, q = idx & 7;
            *(uint4*)(sm + SM_W + (m * WP + q * 8) * 2) = bv[l];
        }
        __syncthreads();

        // HMMA: M=128 N=64 K=64
        const int rsel = lane & 15, csel = (lane >> 4) << 3;
#pragma unroll
        for (int k0 = 0; k0 < 64; k0 += 16) {
            unsigned a0[4], a1[4], b0[4], b1[4];
            LDSM_X4 (a0, Pb + ((mblk      + rsel) * PP + k0 + csel) * 2);
            LDSM_X4 (a1, Pb + ((mblk + 16 + rsel) * PP + k0 + csel) * 2);
            LDSM_X4T(b0, Wb + ((k0 + rsel) * WP + nblk      + csel) * 2);
            LDSM_X4T(b1, Wb + ((k0 + rsel) * WP + nblk + 16 + csel) * 2);
            MMA16816(acc[0][0], a0, b0 + 0);
            MMA16816(acc[0][1], a0, b0 + 2);
            MMA16816(acc[0][2], a0, b1 + 0);
            MMA16816(acc[0][3], a0, b1 + 2);
            MMA16816(acc[1][0], a1, b0 + 0);
            MMA16816(acc[1][1], a1, b0 + 2);
            MMA16816(acc[1][2], a1, b1 + 0);
            MMA16816(acc[1][3], a1, b1 + 2);
        }
        __syncthreads();
    }

    // denominators -> smem
#pragma unroll
    for (int k = 0; k < 16; k++) {
        float v = den[k];
#pragma unroll
        for (int sh = 16; sh; sh >>= 1) v += __shfl_xor_sync(0xffffffffu, v, sh);
        if (lane == 0) denS[wid * 16 + k] = v;
    }
    __syncthreads();

    // epilogue: scale by 1/den, store. Fragment rows: g=lane>>2 (+8); cols 2t,2t+1
    const int g = lane >> 2, t2 = (lane & 3) * 2;
    float inv[4];
#pragma unroll
    for (int i = 0; i < 4; i++) {
        float d = denS[mblk + i * 8 + g];
        inv[i] = d > 0.f ? 1.f / d : 0.f;
    }
#pragma unroll
    for (int mi = 0; mi < 2; mi++)
#pragma unroll
        for (int nj = 0; nj < 4; nj++) {
            int rA = mblk + mi * 16 + g;
            int rB = rA + 8;
            int col = nblk + nj * 8 + t2;
            float ia = inv[mi * 2 + 0], ib = inv[mi * 2 + 1];
            *(float2*)(out + (size_t)(n0 + rA) * (NHEAD * DOUT) + h * DOUT + col) =
                make_float2(acc[mi][nj][0] * ia, acc[mi][nj][1] * ia);
            *(float2*)(out + (size_t)(n0 + rB) * (NHEAD * DOUT) + h * DOUT + col) =
                make_float2(acc[mi][nj][2] * ib, acc[mi][nj][3] * ib);
        }
}

// ---------------------------------------------------------------------------
extern "C" void kernel_launch(void* const* d_in, const int* in_sizes, int n_in,
                              void* d_out, int out_size) {
    (void)in_sizes; (void)n_in; (void)out_size;
    const float* x   = (const float*)d_in[0];
    const int*   adj = (const int*)d_in[1];
    const float* W   = (const float*)d_in[2];
    const float* a1  = (const float*)d_in[3];
    const float* a2  = (const float*)d_in[4];
    float* out = (float*)d_out;

    cudaFuncSetAttribute(attn_mma, cudaFuncAttributeMaxDynamicSharedMemorySize,
                         SMEM_ATT);

    mask_kernel<<<512, 256>>>(adj);
    wh_kernel<<<dim3(32, 8), 256>>>(x, W);
    fvec_kernel<<<4096, 256>>>(a1, a2);
    f2max_kernel<<<8, 256>>>();
    attn_mma<<<dim3(8, 32), 256, SMEM_ATT>>>(out);
}